// round 6
// baseline (speedup 1.0000x reference)
#include <cuda_runtime.h>

#define B_    32
#define H_    64
#define W_    64
#define K_    15
#define ZB_   64
#define NPIX  4096
#define NCH   79
#define ROWB  316                 // NCH * 4 bytes
#define CHUNKS 16
#define PIX_PER_CHUNK 256

#define NXYBLK (CHUNKS * B_)      // 512
#define NZBLK  60                 // 480 (b,k) / 8 per block
#define NBLK   (NXYBLK + NZBLK)   // 572

#define MINL (-150.0f)
#define MAXL (150.0f)
#define DXF  (300.0f/63.0f)

// partial moments: [chunk][b][k] = (sum e, sum e*x, sum e*y, sum e*(x^2+y^2))
__device__ float4 g_part[CHUNKS][B_][K_];
// z results: [b][k] = (loc_z, var_z)
__device__ float2 g_zres[B_][K_];
// completion counter (zero-initialized; last block resets it for graph replay)
__device__ unsigned int g_count;

__constant__ int c_limb[K_] = {0,0,1,1,1,3,4,5,6,2,2,9,10,11,12};
__constant__ int c_sym [K_] = {0,1,2,4,3,6,5,8,7,10,9,12,11,14,13};

// ---------------------------------------------------------------------------
// Final phase: executed by the last block to finish (512 threads).
// ---------------------------------------------------------------------------
__device__ void final_phase(const float* __restrict__ gt,
                            float* __restrict__ out,
                            int total_off, int pose_off) {
    const int tid = threadIdx.x;
    const bool act = (tid < B_ * K_);
    const int b = tid / K_;
    const int k = tid - b * K_;

    __shared__ int   s_idx[B_][K_];
    __shared__ float s_gtz[B_][K_];
    __shared__ float s_px[B_][K_], s_py[B_][K_], s_pz[B_][K_];
    __shared__ float s_v[B_][K_], s_p[B_][K_];
    __shared__ float s_lp[B_][K_];
    __shared__ float red[512];

    float gtx = 0.f, gty = 0.f, gtzc = 0.f;
    float locx = 0.f, locy = 0.f, varxy = 0.f, posxy = 0.f;
    if (act) {
        const float* g3 = gt + (b * K_ + k) * 3;
        gtx  = fminf(fmaxf(g3[0], MINL), MAXL);
        gty  = fminf(fmaxf(g3[1], MINL), MAXL);
        gtzc = fminf(fmaxf(g3[2], MINL), MAXL);
        int ix = min(max((int)rintf((gtx - MINL) / DXF), 0), H_ - 1);
        int iy = min(max((int)rintf((gty - MINL) / DXF), 0), W_ - 1);
        s_idx[b][k] = ix * W_ + iy;
        s_gtz[b][k] = gtzc;

        float4 S = make_float4(0.f, 0.f, 0.f, 0.f);
#pragma unroll
        for (int chn = 0; chn < CHUNKS; ++chn) {
            float4 q = g_part[chn][b][k];
            S.x += q.x; S.y += q.y; S.z += q.z; S.w += q.w;
        }
        locx  = S.y / S.x;
        locy  = S.z / S.x;
        varxy = S.w / S.x - locx * locx - locy * locy;
        const float dx0 = locx - gtx, dy0 = locy - gty;
        posxy = dx0 * dx0 + dy0 * dy0;
        s_px[b][k] = locx; s_py[b][k] = locy;
        s_v[b][k] = varxy; s_p[b][k] = posxy;
    }
    __syncthreads();

    red[tid] = act ? (varxy + posxy) : 0.f;
    __syncthreads();
#pragma unroll
    for (int s = 256; s > 0; s >>= 1) { if (tid < s) red[tid] += red[tid + s]; __syncthreads(); }
    const float s_xy_tot = red[0] + 0.001f;
    __syncthreads();

    float colsq = 0.f;
    if (tid < K_) {
        float cv = 0.f, cp = 0.f;
        for (int bb = 0; bb < B_; ++bb) { cv += s_v[bb][tid]; cp += s_p[bb][tid]; }
        colsq = cv * cv + cp * cp;
    }
    red[tid] = colsq;
    __syncthreads();
#pragma unroll
    for (int s = 256; s > 0; s >>= 1) { if (tid < s) red[tid] += red[tid + s]; __syncthreads(); }
    const float hxy = red[0] * (float)K_ / (s_xy_tot * MAXL);
    __syncthreads();

    float locz = 0.f, varz = 0.f, posz = 0.f;
    if (act) {
        const float2 zr = g_zres[b][k];
        locz = zr.x; varz = zr.y;
        float gte = gtzc;
        const int me = s_idx[b][k];
        for (int kk = 0; kk < K_; ++kk)
            if (s_idx[b][kk] == me) gte = s_gtz[b][kk];
        const float d = locz - gte;
        posz = d * d;
        s_pz[b][k] = locz;
        s_v[b][k] = varz;
        s_p[b][k] = posz;
    }
    __syncthreads();

    red[tid] = act ? (varz + posz) : 0.f;
    __syncthreads();
#pragma unroll
    for (int s = 256; s > 0; s >>= 1) { if (tid < s) red[tid] += red[tid + s]; __syncthreads(); }
    const float s_z_tot = red[0] + 0.001f;
    __syncthreads();

    colsq = 0.f;
    if (tid < K_) {
        float cv = 0.f, cp = 0.f;
        for (int bb = 0; bb < B_; ++bb) { cv += s_v[bb][tid]; cp += s_p[bb][tid]; }
        colsq = cv * cv + cp * cp;
    }
    red[tid] = colsq;
    __syncthreads();
#pragma unroll
    for (int s = 256; s > 0; s >>= 1) { if (tid < s) red[tid] += red[tid + s]; __syncthreads(); }
    const float hz = red[0] * (float)K_ / (s_z_tot * MAXL);
    __syncthreads();

    float ll = 0.f;
    if (act) {
        const int par = c_limb[k];
        const float dxp = locx - s_px[b][par];
        const float dyp = locy - s_py[b][par];
        const float dzp = locz - s_pz[b][par];
        const float lp = sqrtf(dxp * dxp + dyp * dyp + dzp * dzp + 1e-12f);
        const float* g3 = gt + (b * K_ + k) * 3;
        const float* gp = gt + (b * K_ + par) * 3;
        const float dgx = g3[0] - gp[0], dgy = g3[1] - gp[1], dgz = g3[2] - gp[2];
        const float lg = sqrtf(dgx * dgx + dgy * dgy + dgz * dgz + 1e-12f);
        const float dl = lp - lg;
        ll = dl * dl;
        s_lp[b][k] = lp;
    }
    __syncthreads();
    if (act) {
        const float ds = s_lp[b][k] - s_lp[b][c_sym[k]];
        ll += ds * ds;
    }
    red[tid] = ll;
    __syncthreads();
#pragma unroll
    for (int s = 256; s > 0; s >>= 1) { if (tid < s) red[tid] += red[tid + s]; __syncthreads(); }
    const float limbsym = red[0];

    if (tid == 0 && total_off >= 0) out[total_off] = hxy + hz + limbsym;
    if (act && pose_off >= 0) {
        float* o = out + pose_off + (b * K_ + k) * 3;
        o[0] = locx; o[1] = locy; o[2] = locz;
    }
}

// ---------------------------------------------------------------------------
// Fused kernel. XY blocks: vectorized ld.128 staging -> smem -> moments.
// ---------------------------------------------------------------------------
__global__ void __launch_bounds__(512, 4)
k_fused(const float* __restrict__ feat, const float* __restrict__ gt,
        float* __restrict__ out, int total_off, int pose_off) {
    const int tid = threadIdx.x;
    const int blk = blockIdx.x;

    if (blk < NXYBLK) {
        // ---------------- xy partial moments ----------------
        const int b     = blk >> 4;       // 0..31
        const int chunk = blk & 15;       // 0..15

        __shared__ float stage[PIX_PER_CHUNK][16];   // 16 KB (col 15 zeroed)

        // ---- load role: 8 lanes per pixel, one aligned ld.128 each ----
        const int pg = tid >> 3;          // pixel group 0..63 (per tile)
        const int l  = tid & 7;           // lane within pixel

        float4 v[4];
        int    c0[4];
#pragma unroll
        for (int it = 0; it < 4; ++it) {
            const int pl = it * 64 + pg;                 // local pixel 0..255
            const int p  = chunk * PIX_PER_CHUNK + pl;   // global pixel in b
            const size_t fbyte = (size_t)(b * NPIX + p) * (size_t)ROWB;
            const size_t abyte = fbyte & ~(size_t)15;    // 16B align down
            v[it]  = *(const float4*)((const char*)feat + abyte + (size_t)l * 16);
            c0[it] = l * 4 - (int)((fbyte & 15) >> 2);   // channel of v[it].x
        }
#pragma unroll
        for (int it = 0; it < 4; ++it) {
            const int pl = it * 64 + pg;
            if (l == 7) stage[pl][15] = 0.f;             // dummy column
            const int c = c0[it];
            if (c + 0 >= 0 && c + 0 < K_) stage[pl][c + 0] = v[it].x;
            if (c + 1 >= 0 && c + 1 < K_) stage[pl][c + 1] = v[it].y;
            if (c + 2 >= 0 && c + 2 < K_) stage[pl][c + 2] = v[it].z;
            if (c + 3 >= 0 && c + 3 < K_) stage[pl][c + 3] = v[it].w;
        }
        __syncthreads();

        // ---- compute role: thread (c, g) handles 8 pixels ----
        const int c = tid & 15;
        const int g = tid >> 4;           // 0..31
        float S0 = 0.f, S1x = 0.f, S1y = 0.f, S2 = 0.f;
#pragma unroll
        for (int h = 0; h < 8; ++h) {
            const int pl = h * 32 + g;
            const int p  = chunk * PIX_PER_CHUNK + pl;
            const float e = __expf(stage[pl][c]);
            const float x = MINL + (float)(p >> 6) * DXF;
            const float y = MINL + (float)(p & 63) * DXF;
            S0 += e;
            S1x = fmaf(e, x, S1x);
            S1y = fmaf(e, y, S1y);
            S2  = fmaf(e, fmaf(x, x, y * y), S2);
        }

        __shared__ float4 sm[32][16];
        sm[g][c] = make_float4(S0, S1x, S1y, S2);
        __syncthreads();
#pragma unroll
        for (int s = 16; s > 0; s >>= 1) {
            if (g < s) {
                float4 a = sm[g][c], q = sm[g + s][c];
                sm[g][c] = make_float4(a.x + q.x, a.y + q.y, a.z + q.z, a.w + q.w);
            }
            __syncthreads();
        }
        if (g == 0 && c < K_) g_part[chunk][b][c] = sm[0][c];
    } else {
        // ---------------- z softmax: 8 (b,k) per block ----------------
        const int zi = blk - NXYBLK;      // 0..59
        const int s  = tid >> 6;          // sub-block 0..7
        const int zb = tid & 63;          // z bin
        const int bk = zi * 8 + s;        // 0..479
        const int b  = bk / K_;
        const int k  = bk - b * K_;

        __shared__ int s_pix[8];
        if (zb == 0) {
            const float* g3 = gt + bk * 3;
            const float gtx = fminf(fmaxf(g3[0], MINL), MAXL);
            const float gty = fminf(fmaxf(g3[1], MINL), MAXL);
            int ix = min(max((int)rintf((gtx - MINL) / DXF), 0), H_ - 1);
            int iy = min(max((int)rintf((gty - MINL) / DXF), 0), W_ - 1);
            s_pix[s] = ix * W_ + iy;
        }
        __syncthreads();

        const float* fz = feat + ((size_t)(b * NPIX + s_pix[s])) * NCH + K_;
        const float e  = __expf(fz[zb]);
        const float zm = MINL + (float)zb * DXF;
        float S0 = e;
        float S1 = e * zm;
        float S2 = e * zm * zm;

#pragma unroll
        for (int o = 16; o > 0; o >>= 1) {
            S0 += __shfl_down_sync(0xffffffffu, S0, o);
            S1 += __shfl_down_sync(0xffffffffu, S1, o);
            S2 += __shfl_down_sync(0xffffffffu, S2, o);
        }
        __shared__ float3 ws[16];
        if ((tid & 31) == 0) ws[tid >> 5] = make_float3(S0, S1, S2);
        __syncthreads();
        if (zb == 0) {
            const float3 a = ws[2 * s], q = ws[2 * s + 1];
            const float T0 = a.x + q.x;
            const float T1 = a.y + q.y;
            const float T2 = a.z + q.z;
            const float locz = T1 / T0;
            const float varz = T2 / T0 - locz * locz;
            g_zres[b][k] = make_float2(locz, varz);
        }
    }

    // ---------------- completion protocol ----------------
    __threadfence();
    __shared__ bool s_last;
    if (tid == 0) {
        const unsigned int prev = atomicAdd(&g_count, 1u);
        s_last = (prev == NBLK - 1);
    }
    __syncthreads();

    if (s_last) {
        if (tid == 0) g_count = 0;        // reset for next graph replay
        __threadfence();
        final_phase(gt, out, total_off, pose_off);
    }
}

// ---------------------------------------------------------------------------
extern "C" void kernel_launch(void* const* d_in, const int* in_sizes, int n_in,
                              void* d_out, int out_size) {
    const float* feat = (const float*)d_in[0];   // (32,64,64,79)
    const float* gt   = (const float*)d_in[1];   // (32,15,3)
    float* out = (float*)d_out;

    int total_off, pose_off;
    if (out_size >= 1441)      { total_off = 0;  pose_off = 1;  }
    else if (out_size == 1440) { total_off = -1; pose_off = 0;  }
    else                       { total_off = 0;  pose_off = -1; }

    k_fused<<<NBLK, 512>>>(feat, gt, out, total_off, pose_off);
}

// round 7
// speedup vs baseline: 1.2593x; 1.2593x over previous
#include <cuda_runtime.h>

#define B_    32
#define H_    64
#define W_    64
#define K_    15
#define ZB_   64
#define NPIX  4096
#define NCH   79
#define CHUNKS 8
#define PIX_PER_CHUNK 512

#define NZBLK  60                 // 480 (b,k) / 8 per block (scheduled first)
#define NXYBLK (CHUNKS * B_)      // 256
#define NBLK   (NZBLK + NXYBLK)   // 316

#define MINL (-150.0f)
#define MAXL (150.0f)
#define DXF  (300.0f/63.0f)

// partial moments: [chunk][b][k] = (sum e, sum e*x, sum e*y, sum e*(x^2+y^2))
__device__ float4 g_part[CHUNKS][B_][K_];
// z results: [b][k] = (loc_z, var_z)
__device__ float2 g_zres[B_][K_];
// completion counter (zero-initialized; last block resets it for graph replay)
__device__ unsigned int g_count;

__constant__ int c_limb[K_] = {0,0,1,1,1,3,4,5,6,2,2,9,10,11,12};
__constant__ int c_sym [K_] = {0,1,2,4,3,6,5,8,7,10,9,12,11,14,13};

// ---------------------------------------------------------------------------
// Final phase: executed by the last block to finish (512 threads).
// ---------------------------------------------------------------------------
__device__ void final_phase(const float* __restrict__ gt,
                            float* __restrict__ out,
                            int total_off, int pose_off) {
    const int tid = threadIdx.x;
    const bool act = (tid < B_ * K_);
    const int b = tid / K_;
    const int k = tid - b * K_;

    __shared__ int   s_idx[B_][K_];
    __shared__ float s_gtz[B_][K_];
    __shared__ float s_px[B_][K_], s_py[B_][K_], s_pz[B_][K_];
    __shared__ float s_v[B_][K_], s_p[B_][K_];
    __shared__ float s_lp[B_][K_];
    __shared__ float red[512];

    float gtx = 0.f, gty = 0.f, gtzc = 0.f;
    float locx = 0.f, locy = 0.f, varxy = 0.f, posxy = 0.f;
    if (act) {
        const float* g3 = gt + (b * K_ + k) * 3;
        gtx  = fminf(fmaxf(g3[0], MINL), MAXL);
        gty  = fminf(fmaxf(g3[1], MINL), MAXL);
        gtzc = fminf(fmaxf(g3[2], MINL), MAXL);
        int ix = min(max((int)rintf((gtx - MINL) / DXF), 0), H_ - 1);
        int iy = min(max((int)rintf((gty - MINL) / DXF), 0), W_ - 1);
        s_idx[b][k] = ix * W_ + iy;
        s_gtz[b][k] = gtzc;

        float4 S = make_float4(0.f, 0.f, 0.f, 0.f);
#pragma unroll
        for (int chn = 0; chn < CHUNKS; ++chn) {
            float4 q = g_part[chn][b][k];
            S.x += q.x; S.y += q.y; S.z += q.z; S.w += q.w;
        }
        locx  = S.y / S.x;
        locy  = S.z / S.x;
        varxy = S.w / S.x - locx * locx - locy * locy;
        const float dx0 = locx - gtx, dy0 = locy - gty;
        posxy = dx0 * dx0 + dy0 * dy0;
        s_px[b][k] = locx; s_py[b][k] = locy;
        s_v[b][k] = varxy; s_p[b][k] = posxy;
    }
    __syncthreads();

    red[tid] = act ? (varxy + posxy) : 0.f;
    __syncthreads();
#pragma unroll
    for (int s = 256; s > 0; s >>= 1) { if (tid < s) red[tid] += red[tid + s]; __syncthreads(); }
    const float s_xy_tot = red[0] + 0.001f;
    __syncthreads();

    float colsq = 0.f;
    if (tid < K_) {
        float cv = 0.f, cp = 0.f;
        for (int bb = 0; bb < B_; ++bb) { cv += s_v[bb][tid]; cp += s_p[bb][tid]; }
        colsq = cv * cv + cp * cp;
    }
    red[tid] = colsq;
    __syncthreads();
#pragma unroll
    for (int s = 256; s > 0; s >>= 1) { if (tid < s) red[tid] += red[tid + s]; __syncthreads(); }
    const float hxy = red[0] * (float)K_ / (s_xy_tot * MAXL);
    __syncthreads();

    float locz = 0.f, varz = 0.f, posz = 0.f;
    if (act) {
        const float2 zr = g_zres[b][k];
        locz = zr.x; varz = zr.y;
        float gte = gtzc;
        const int me = s_idx[b][k];
        for (int kk = 0; kk < K_; ++kk)
            if (s_idx[b][kk] == me) gte = s_gtz[b][kk];
        const float d = locz - gte;
        posz = d * d;
        s_pz[b][k] = locz;
        s_v[b][k] = varz;
        s_p[b][k] = posz;
    }
    __syncthreads();

    red[tid] = act ? (varz + posz) : 0.f;
    __syncthreads();
#pragma unroll
    for (int s = 256; s > 0; s >>= 1) { if (tid < s) red[tid] += red[tid + s]; __syncthreads(); }
    const float s_z_tot = red[0] + 0.001f;
    __syncthreads();

    colsq = 0.f;
    if (tid < K_) {
        float cv = 0.f, cp = 0.f;
        for (int bb = 0; bb < B_; ++bb) { cv += s_v[bb][tid]; cp += s_p[bb][tid]; }
        colsq = cv * cv + cp * cp;
    }
    red[tid] = colsq;
    __syncthreads();
#pragma unroll
    for (int s = 256; s > 0; s >>= 1) { if (tid < s) red[tid] += red[tid + s]; __syncthreads(); }
    const float hz = red[0] * (float)K_ / (s_z_tot * MAXL);
    __syncthreads();

    float ll = 0.f;
    if (act) {
        const int par = c_limb[k];
        const float dxp = locx - s_px[b][par];
        const float dyp = locy - s_py[b][par];
        const float dzp = locz - s_pz[b][par];
        const float lp = sqrtf(dxp * dxp + dyp * dyp + dzp * dzp + 1e-12f);
        const float* g3 = gt + (b * K_ + k) * 3;
        const float* gp = gt + (b * K_ + par) * 3;
        const float dgx = g3[0] - gp[0], dgy = g3[1] - gp[1], dgz = g3[2] - gp[2];
        const float lg = sqrtf(dgx * dgx + dgy * dgy + dgz * dgz + 1e-12f);
        const float dl = lp - lg;
        ll = dl * dl;
        s_lp[b][k] = lp;
    }
    __syncthreads();
    if (act) {
        const float ds = s_lp[b][k] - s_lp[b][c_sym[k]];
        ll += ds * ds;
    }
    red[tid] = ll;
    __syncthreads();
#pragma unroll
    for (int s = 256; s > 0; s >>= 1) { if (tid < s) red[tid] += red[tid + s]; __syncthreads(); }
    const float limbsym = red[0];

    if (tid == 0 && total_off >= 0) out[total_off] = hxy + hz + limbsym;
    if (act && pose_off >= 0) {
        float* o = out + pose_off + (b * K_ + k) * 3;
        o[0] = locx; o[1] = locy; o[2] = locz;
    }
}

// ---------------------------------------------------------------------------
// Fused kernel. z blocks first (fast), then xy blocks with 16-deep LDG batch.
// ---------------------------------------------------------------------------
__global__ void __launch_bounds__(512, 2)
k_fused(const float* __restrict__ feat, const float* __restrict__ gt,
        float* __restrict__ out, int total_off, int pose_off) {
    const int tid = threadIdx.x;
    const int blk = blockIdx.x;

    if (blk >= NZBLK) {
        // ---------------- xy partial moments ----------------
        const int xyi   = blk - NZBLK;
        const int b     = xyi >> 3;       // 0..31
        const int chunk = xyi & 7;        // 0..7
        const int c     = tid & 15;       // channel (15 is a dummy lane)
        const int g     = tid >> 4;       // pixel group 0..31
        const int p0    = chunk * PIX_PER_CHUNK;

        // batch-load 16 values into registers (independent LDGs, MLP=16)
        const float* base = feat + (size_t)(b * NPIX + p0 + g) * NCH + c;
        float vals[16];
#pragma unroll
        for (int it = 0; it < 16; ++it)
            vals[it] = base[it * 32 * NCH];

        float S0 = 0.f, S1x = 0.f, S1y = 0.f, S2 = 0.f;
#pragma unroll
        for (int it = 0; it < 16; ++it) {
            const int p = p0 + it * 32 + g;
            const float e = __expf(vals[it]);
            const float x = MINL + (float)(p >> 6) * DXF;
            const float y = MINL + (float)(p & 63) * DXF;
            S0 += e;
            S1x = fmaf(e, x, S1x);
            S1y = fmaf(e, y, S1y);
            S2  = fmaf(e, fmaf(x, x, y * y), S2);
        }

        // reduce over g: shuffle combines the warp's two g-values per c,
        // then 16 warps' partials summed by 16 threads.
        S0  += __shfl_down_sync(0xffffffffu, S0, 16);
        S1x += __shfl_down_sync(0xffffffffu, S1x, 16);
        S1y += __shfl_down_sync(0xffffffffu, S1y, 16);
        S2  += __shfl_down_sync(0xffffffffu, S2, 16);

        __shared__ float4 sm4[16][16];
        if ((tid & 31) < 16) sm4[tid >> 5][c] = make_float4(S0, S1x, S1y, S2);
        __syncthreads();
        if (tid < K_) {
            float4 A = make_float4(0.f, 0.f, 0.f, 0.f);
#pragma unroll
            for (int w = 0; w < 16; ++w) {
                const float4 q = sm4[w][tid];
                A.x += q.x; A.y += q.y; A.z += q.z; A.w += q.w;
            }
            g_part[chunk][b][tid] = A;
        }
    } else {
        // ---------------- z softmax: 8 (b,k) per block ----------------
        const int zi = blk;               // 0..59
        const int s  = tid >> 6;          // sub-block 0..7
        const int zb = tid & 63;          // z bin
        const int bk = zi * 8 + s;        // 0..479
        const int b  = bk / K_;
        const int k  = bk - b * K_;

        __shared__ int s_pix[8];
        if (zb == 0) {
            const float* g3 = gt + bk * 3;
            const float gtx = fminf(fmaxf(g3[0], MINL), MAXL);
            const float gty = fminf(fmaxf(g3[1], MINL), MAXL);
            int ix = min(max((int)rintf((gtx - MINL) / DXF), 0), H_ - 1);
            int iy = min(max((int)rintf((gty - MINL) / DXF), 0), W_ - 1);
            s_pix[s] = ix * W_ + iy;
        }
        __syncthreads();

        const float* fz = feat + ((size_t)(b * NPIX + s_pix[s])) * NCH + K_;
        const float e  = __expf(fz[zb]);
        const float zm = MINL + (float)zb * DXF;
        float S0 = e;
        float S1 = e * zm;
        float S2 = e * zm * zm;

#pragma unroll
        for (int o = 16; o > 0; o >>= 1) {
            S0 += __shfl_down_sync(0xffffffffu, S0, o);
            S1 += __shfl_down_sync(0xffffffffu, S1, o);
            S2 += __shfl_down_sync(0xffffffffu, S2, o);
        }
        __shared__ float3 ws[16];
        if ((tid & 31) == 0) ws[tid >> 5] = make_float3(S0, S1, S2);
        __syncthreads();
        if (zb == 0) {
            const float3 a = ws[2 * s], q = ws[2 * s + 1];
            const float T0 = a.x + q.x;
            const float T1 = a.y + q.y;
            const float T2 = a.z + q.z;
            const float locz = T1 / T0;
            const float varz = T2 / T0 - locz * locz;
            g_zres[b][k] = make_float2(locz, varz);
        }
    }

    // ---------------- completion protocol ----------------
    __threadfence();
    __shared__ bool s_last;
    if (tid == 0) {
        const unsigned int prev = atomicAdd(&g_count, 1u);
        s_last = (prev == NBLK - 1);
    }
    __syncthreads();

    if (s_last) {
        if (tid == 0) g_count = 0;        // reset for next graph replay
        __threadfence();
        final_phase(gt, out, total_off, pose_off);
    }
}

// ---------------------------------------------------------------------------
extern "C" void kernel_launch(void* const* d_in, const int* in_sizes, int n_in,
                              void* d_out, int out_size) {
    const float* feat = (const float*)d_in[0];   // (32,64,64,79)
    const float* gt   = (const float*)d_in[1];   // (32,15,3)
    float* out = (float*)d_out;

    int total_off, pose_off;
    if (out_size >= 1441)      { total_off = 0;  pose_off = 1;  }
    else if (out_size == 1440) { total_off = -1; pose_off = 0;  }
    else                       { total_off = 0;  pose_off = -1; }

    k_fused<<<NBLK, 512>>>(feat, gt, out, total_off, pose_off);
}

// round 10
// speedup vs baseline: 1.2759x; 1.0132x over previous
#include <cuda_runtime.h>

#define B_    32
#define H_    64
#define W_    64
#define K_    15
#define ZB_   64
#define NPIX  4096
#define NCH   79
#define CHUNKS 4
#define PIX_PER_CHUNK 1024

#define NZBLK  60                 // z blocks scheduled first
#define NXYBLK (CHUNKS * B_)      // 128
#define NBLK   (NZBLK + NXYBLK)   // 188

#define MINL (-150.0f)
#define MAXL (150.0f)
#define DXF  (300.0f/63.0f)

// partial moments: [chunk][b][k] = (sum e, sum e*x, sum e*y, sum e*(x^2+y^2))
__device__ float4 g_part[CHUNKS][B_][K_];
// z results: [b][k] = (loc_z, var_z)
__device__ float2 g_zres[B_][K_];
// two-level completion counters (zero-initialized; reset in-kernel for replay)
__device__ unsigned int g_cnt8[8 * 32];   // stride 32 ints = 128B apart
__device__ unsigned int g_master;

__constant__ int c_limb[K_] = {0,0,1,1,1,3,4,5,6,2,2,9,10,11,12};
__constant__ int c_sym [K_] = {0,1,2,4,3,6,5,8,7,10,9,12,11,14,13};

// ---------------------------------------------------------------------------
// Block-wide sum over 512 threads via shuffles; 3 barriers.
// ---------------------------------------------------------------------------
__device__ __forceinline__ float block_sum512(float v) {
    __shared__ float sm[16];
    const int tid = threadIdx.x;
#pragma unroll
    for (int o = 16; o > 0; o >>= 1) v += __shfl_down_sync(0xffffffffu, v, o);
    __syncthreads();                       // protect sm reuse across calls
    if ((tid & 31) == 0) sm[tid >> 5] = v;
    __syncthreads();
    float w = 0.f;
    if (tid < 32) {
        w = (tid < 16) ? sm[tid] : 0.f;
#pragma unroll
        for (int o = 8; o > 0; o >>= 1) w += __shfl_down_sync(0xffffffffu, w, o);
        if (tid == 0) sm[0] = w;
    }
    __syncthreads();
    return sm[0];
}

// ---------------------------------------------------------------------------
// Final phase: executed by the globally-last block (512 threads).
// ---------------------------------------------------------------------------
__device__ void final_phase(const float* __restrict__ gt,
                            float* __restrict__ out,
                            int total_off, int pose_off) {
    const int tid = threadIdx.x;
    const bool act = (tid < B_ * K_);
    const int b = tid / K_;
    const int k = tid - b * K_;

    __shared__ int   s_idx[B_][K_];
    __shared__ float s_gtz[B_][K_];
    __shared__ float s_px[B_][K_], s_py[B_][K_], s_pz[B_][K_];
    __shared__ float s_v[B_][K_], s_p[B_][K_];
    __shared__ float s_lp[B_][K_];

    float gtx = 0.f, gty = 0.f, gtzc = 0.f;
    float locx = 0.f, locy = 0.f, varxy = 0.f, posxy = 0.f;
    if (act) {
        const float* g3 = gt + (b * K_ + k) * 3;
        gtx  = fminf(fmaxf(g3[0], MINL), MAXL);
        gty  = fminf(fmaxf(g3[1], MINL), MAXL);
        gtzc = fminf(fmaxf(g3[2], MINL), MAXL);
        int ix = min(max((int)rintf((gtx - MINL) / DXF), 0), H_ - 1);
        int iy = min(max((int)rintf((gty - MINL) / DXF), 0), W_ - 1);
        s_idx[b][k] = ix * W_ + iy;
        s_gtz[b][k] = gtzc;

        float4 S = make_float4(0.f, 0.f, 0.f, 0.f);
#pragma unroll
        for (int chn = 0; chn < CHUNKS; ++chn) {
            float4 q = g_part[chn][b][k];
            S.x += q.x; S.y += q.y; S.z += q.z; S.w += q.w;
        }
        locx  = S.y / S.x;
        locy  = S.z / S.x;
        varxy = S.w / S.x - locx * locx - locy * locy;
        const float dx0 = locx - gtx, dy0 = locy - gty;
        posxy = dx0 * dx0 + dy0 * dy0;
        s_px[b][k] = locx; s_py[b][k] = locy;
        s_v[b][k] = varxy; s_p[b][k] = posxy;
    }
    __syncthreads();

    const float s_xy_tot = block_sum512(act ? (varxy + posxy) : 0.f) + 0.001f;

    float colsq = 0.f;
    if (tid < K_) {
        float cv = 0.f, cp = 0.f;
        for (int bb = 0; bb < B_; ++bb) { cv += s_v[bb][tid]; cp += s_p[bb][tid]; }
        colsq = cv * cv + cp * cp;
    }
    const float hxy = block_sum512(colsq) * (float)K_ / (s_xy_tot * MAXL);

    float locz = 0.f, varz = 0.f, posz = 0.f;
    if (act) {
        const float2 zr = g_zres[b][k];
        locz = zr.x; varz = zr.y;
        float gte = gtzc;
        const int me = s_idx[b][k];
        for (int kk = 0; kk < K_; ++kk)
            if (s_idx[b][kk] == me) gte = s_gtz[b][kk];
        const float d = locz - gte;
        posz = d * d;
        s_pz[b][k] = locz;
        s_v[b][k] = varz;
        s_p[b][k] = posz;
    }
    __syncthreads();

    const float s_z_tot = block_sum512(act ? (varz + posz) : 0.f) + 0.001f;

    colsq = 0.f;
    if (tid < K_) {
        float cv = 0.f, cp = 0.f;
        for (int bb = 0; bb < B_; ++bb) { cv += s_v[bb][tid]; cp += s_p[bb][tid]; }
        colsq = cv * cv + cp * cp;
    }
    const float hz = block_sum512(colsq) * (float)K_ / (s_z_tot * MAXL);

    float ll = 0.f;
    if (act) {
        const int par = c_limb[k];
        const float dxp = locx - s_px[b][par];
        const float dyp = locy - s_py[b][par];
        const float dzp = locz - s_pz[b][par];
        const float lp = sqrtf(dxp * dxp + dyp * dyp + dzp * dzp + 1e-12f);
        const float* g3 = gt + (b * K_ + k) * 3;
        const float* gp = gt + (b * K_ + par) * 3;
        const float dgx = g3[0] - gp[0], dgy = g3[1] - gp[1], dgz = g3[2] - gp[2];
        const float lg = sqrtf(dgx * dgx + dgy * dgy + dgz * dgz + 1e-12f);
        const float dl = lp - lg;
        ll = dl * dl;
        s_lp[b][k] = lp;
    }
    __syncthreads();
    if (act) {
        const float ds = s_lp[b][k] - s_lp[b][c_sym[k]];
        ll += ds * ds;
    }
    const float limbsym = block_sum512(ll);

    if (tid == 0 && total_off >= 0) out[total_off] = hxy + hz + limbsym;
    if (act && pose_off >= 0) {
        float* o = out + pose_off + (b * K_ + k) * 3;
        o[0] = locx; o[1] = locy; o[2] = locz;
    }
}

// ---------------------------------------------------------------------------
// Fused kernel. z blocks first, then 128 xy blocks (32 pixels/thread,
// two 16-deep LDG batches). Two-level completion; last block finalizes.
// ---------------------------------------------------------------------------
__global__ void __launch_bounds__(512, 2)
k_fused(const float* __restrict__ feat, const float* __restrict__ gt,
        float* __restrict__ out, int total_off, int pose_off) {
    const int tid = threadIdx.x;
    const int blk = blockIdx.x;

    if (blk >= NZBLK) {
        // ---------------- xy partial moments ----------------
        const int xyi   = blk - NZBLK;
        const int b     = xyi >> 2;       // 0..31
        const int chunk = xyi & 3;        // 0..3
        const int c     = tid & 15;       // channel (15 is a dummy lane)
        const int g     = tid >> 4;       // pixel group 0..31

        float S0 = 0.f, S1x = 0.f, S1y = 0.f, S2 = 0.f;
#pragma unroll 1
        for (int half = 0; half < 2; ++half) {
            const int pbase = chunk * PIX_PER_CHUNK + half * 512;
            const float* base = feat + (size_t)(b * NPIX + pbase + g) * NCH + c;
            float vals[16];
#pragma unroll
            for (int it = 0; it < 16; ++it)
                vals[it] = base[(size_t)it * 32 * NCH];
#pragma unroll
            for (int it = 0; it < 16; ++it) {
                const int p = pbase + it * 32 + g;
                const float e = __expf(vals[it]);
                const float x = MINL + (float)(p >> 6) * DXF;
                const float y = MINL + (float)(p & 63) * DXF;
                S0 += e;
                S1x = fmaf(e, x, S1x);
                S1y = fmaf(e, y, S1y);
                S2  = fmaf(e, fmaf(x, x, y * y), S2);
            }
        }

        // reduce over g: warp shuffle (two g per warp), then 16 warps by 15 thr
        S0  += __shfl_down_sync(0xffffffffu, S0, 16);
        S1x += __shfl_down_sync(0xffffffffu, S1x, 16);
        S1y += __shfl_down_sync(0xffffffffu, S1y, 16);
        S2  += __shfl_down_sync(0xffffffffu, S2, 16);

        __shared__ float4 sm4[16][16];
        if ((tid & 31) < 16) sm4[tid >> 5][c] = make_float4(S0, S1x, S1y, S2);
        __syncthreads();
        if (tid < K_) {
            float4 A = make_float4(0.f, 0.f, 0.f, 0.f);
#pragma unroll
            for (int w = 0; w < 16; ++w) {
                const float4 q = sm4[w][tid];
                A.x += q.x; A.y += q.y; A.z += q.z; A.w += q.w;
            }
            g_part[chunk][b][tid] = A;
        }
    } else {
        // ---------------- z softmax: 8 (b,k) per block ----------------
        const int zi = blk;               // 0..59
        const int s  = tid >> 6;          // sub-block 0..7
        const int zb = tid & 63;          // z bin
        const int bk = zi * 8 + s;        // 0..479
        const int b  = bk / K_;
        const int k  = bk - b * K_;

        __shared__ int s_pix[8];
        if (zb == 0) {
            const float* g3 = gt + bk * 3;
            const float gtx = fminf(fmaxf(g3[0], MINL), MAXL);
            const float gty = fminf(fmaxf(g3[1], MINL), MAXL);
            int ix = min(max((int)rintf((gtx - MINL) / DXF), 0), H_ - 1);
            int iy = min(max((int)rintf((gty - MINL) / DXF), 0), W_ - 1);
            s_pix[s] = ix * W_ + iy;
        }
        __syncthreads();

        const float* fz = feat + ((size_t)(b * NPIX + s_pix[s])) * NCH + K_;
        const float e  = __expf(fz[zb]);
        const float zm = MINL + (float)zb * DXF;
        float S0 = e;
        float S1 = e * zm;
        float S2 = e * zm * zm;

#pragma unroll
        for (int o = 16; o > 0; o >>= 1) {
            S0 += __shfl_down_sync(0xffffffffu, S0, o);
            S1 += __shfl_down_sync(0xffffffffu, S1, o);
            S2 += __shfl_down_sync(0xffffffffu, S2, o);
        }
        __shared__ float3 ws[16];
        if ((tid & 31) == 0) ws[tid >> 5] = make_float3(S0, S1, S2);
        __syncthreads();
        if (zb == 0) {
            const float3 a = ws[2 * s], q = ws[2 * s + 1];
            const float T0 = a.x + q.x;
            const float T1 = a.y + q.y;
            const float T2 = a.z + q.z;
            const float locz = T1 / T0;
            const float varz = T2 / T0 - locz * locz;
            g_zres[b][k] = make_float2(locz, varz);
        }
    }

    // ---------------- two-level completion protocol ----------------
    __threadfence();
    __shared__ bool s_last;
    if (tid == 0) {
        bool last = false;
        const int r = blk & 7;
        const unsigned int gsz = (unsigned int)((NBLK - 1 - r) / 8 + 1);
        const unsigned int prev = atomicAdd(&g_cnt8[r * 32], 1u);
        if (prev == gsz - 1u) {
            g_cnt8[r * 32] = 0;                    // reset own group counter
            __threadfence();
            const unsigned int mp = atomicAdd(&g_master, 1u);
            if (mp == 7u) { last = true; g_master = 0; }
        }
        s_last = last;
    }
    __syncthreads();

    if (s_last) {
        __threadfence();
        final_phase(gt, out, total_off, pose_off);
    }
}

// ---------------------------------------------------------------------------
extern "C" void kernel_launch(void* const* d_in, const int* in_sizes, int n_in,
                              void* d_out, int out_size) {
    const float* feat = (const float*)d_in[0];   // (32,64,64,79)
    const float* gt   = (const float*)d_in[1];   // (32,15,3)
    float* out = (float*)d_out;

    int total_off, pose_off;
    if (out_size >= 1441)      { total_off = 0;  pose_off = 1;  }
    else if (out_size == 1440) { total_off = -1; pose_off = 0;  }
    else                       { total_off = 0;  pose_off = -1; }

    k_fused<<<NBLK, 512>>>(feat, gt, out, total_off, pose_off);
}